// round 14
// baseline (speedup 1.0000x reference)
#include <cuda_runtime.h>
#include <cstdint>

// MMI softmax loss — collapsed gather form, single launch, warp-per-block.
// FINAL: verbatim resubmission of the best-measured kernel (6.624us, R7).
// Five structurally different variants all measured >= this; the wall clock
// is dominated by a ~6.6us graph-replay/launch floor, with true device work
// ~0.5us (10,240 scattered f32 gathers, all pipes ~0%).
//
//   out = -(1/2048) * sum_d  emb[d, t_d] / (sum_{j=1..4} emb[d + j*2048, t_d])
//
// 64 single-warp blocks (no __syncthreads, no smem on the main path) compute
// warp partials; the last-arriving warp (gpu-scope acq_rel counter, no
// __threadfence -> no CCTL.IVALL) folds the 64 partials in a fixed tree
// (bit-deterministic) and writes the scalar, then re-arms the counter for
// graph replay.

#define DIM   2048
#define NCLS  32000LL
#define NBLK  64
#define TPB   32    // NBLK * TPB == DIM, one d per thread, one warp per block

__device__ float        g_partial[NBLK];
__device__ unsigned int g_count = 0;   // always left at 0 by the last warp

__global__ void mmi_fused_kernel(const float* __restrict__ emb,
                                 const int* __restrict__ tgt,
                                 float* __restrict__ out) {
    const int lane = threadIdx.x;
    const int d = blockIdx.x * TPB + lane;          // 0..2047, exact cover

    const int t = __ldg(&tgt[d]);                   // coalesced: 1 line/warp
    const float* col = emb + (long long)t;

    // 5 independent gathers (MLP=5 per thread; latency overlapped)
    const float ex = __ldg(col + (long long)d * NCLS);
    const float c0 = __ldg(col + (long long)(d + 1 * DIM) * NCLS);
    const float c1 = __ldg(col + (long long)(d + 2 * DIM) * NCLS);
    const float c2 = __ldg(col + (long long)(d + 3 * DIM) * NCLS);
    const float c3 = __ldg(col + (long long)(d + 4 * DIM) * NCLS);

    float v = ex / (((c0 + c1) + c2) + c3);

    // intra-warp reduce (fixed tree)
    #pragma unroll
    for (int o = 16; o; o >>= 1)
        v += __shfl_xor_sync(0xffffffffu, v, o);

    // Lane 0: publish partial to L2 (st.global.cg — bypasses L1), arrive with
    // gpu-scope acq_rel atomic (release orders the store; acquire covers the
    // last warp's reads). No barriers, no smem, no MEMBAR on this path.
    unsigned prev = 0;
    if (lane == 0) {
        asm volatile(
            "st.global.cg.f32 [%1], %2;\n\t"
            "atom.acq_rel.gpu.global.add.u32 %0, [%3], 1;\n\t"
            : "=r"(prev)
            : "l"(&g_partial[blockIdx.x]), "f"(v), "l"(&g_count)
            : "memory");
    }
    // broadcast last-arriver flag to the whole warp (warp-uniform branch)
    const bool is_last =
        (__shfl_sync(0xffffffffu, prev, 0) == (unsigned)(NBLK - 1));

    if (is_last) {
        // fold 64 partials: 2 acquire loads per lane, fixed order -> deterministic
        float p0, p1;
        asm volatile("ld.acquire.gpu.global.f32 %0, [%1];"
                     : "=f"(p0) : "l"(&g_partial[lane]) : "memory");
        asm volatile("ld.acquire.gpu.global.f32 %0, [%1];"
                     : "=f"(p1) : "l"(&g_partial[lane + 32]) : "memory");
        float p = p0 + p1;
        #pragma unroll
        for (int o = 16; o; o >>= 1)
            p += __shfl_xor_sync(0xffffffffu, p, o);
        if (lane == 0) {
            *out = -(p / (float)DIM);
            g_count = 0;   // re-arm; visible at kernel boundary before next replay
        }
    }
}

extern "C" void kernel_launch(void* const* d_in, const int* in_sizes, int n_in,
                              void* d_out, int out_size) {
    const float* emb = (const float*)d_in[0];   // embeddings [10240, 32000] f32
    const int*   tgt = (const int*)d_in[1];     // targets [2048] i32

    mmi_fused_kernel<<<NBLK, TPB>>>(emb, tgt, (float*)d_out);
}

// round 15
// speedup vs baseline: 1.0048x; 1.0048x over previous
#include <cuda_runtime.h>
#include <cstdint>

// MMI softmax loss — collapsed gather form, single launch, warp-per-block.
// FINAL: verbatim resubmission of the best-measured kernel (6.624us, R7).
// Five structurally different variants all measured >= this; the wall clock
// is dominated by a ~6.6us graph-replay/launch floor, with true device work
// ~0.5us (10,240 scattered f32 gathers, all pipes ~0%).
//
//   out = -(1/2048) * sum_d  emb[d, t_d] / (sum_{j=1..4} emb[d + j*2048, t_d])
//
// 64 single-warp blocks (no __syncthreads, no smem on the main path) compute
// warp partials; the last-arriving warp (gpu-scope acq_rel counter, no
// __threadfence -> no CCTL.IVALL) folds the 64 partials in a fixed tree
// (bit-deterministic) and writes the scalar, then re-arms the counter for
// graph replay.

#define DIM   2048
#define NCLS  32000LL
#define NBLK  64
#define TPB   32    // NBLK * TPB == DIM, one d per thread, one warp per block

__device__ float        g_partial[NBLK];
__device__ unsigned int g_count = 0;   // always left at 0 by the last warp

__global__ void mmi_fused_kernel(const float* __restrict__ emb,
                                 const int* __restrict__ tgt,
                                 float* __restrict__ out) {
    const int lane = threadIdx.x;
    const int d = blockIdx.x * TPB + lane;          // 0..2047, exact cover

    const int t = __ldg(&tgt[d]);                   // coalesced: 1 line/warp
    const float* col = emb + (long long)t;

    // 5 independent gathers (MLP=5 per thread; latency overlapped)
    const float ex = __ldg(col + (long long)d * NCLS);
    const float c0 = __ldg(col + (long long)(d + 1 * DIM) * NCLS);
    const float c1 = __ldg(col + (long long)(d + 2 * DIM) * NCLS);
    const float c2 = __ldg(col + (long long)(d + 3 * DIM) * NCLS);
    const float c3 = __ldg(col + (long long)(d + 4 * DIM) * NCLS);

    float v = ex / (((c0 + c1) + c2) + c3);

    // intra-warp reduce (fixed tree)
    #pragma unroll
    for (int o = 16; o; o >>= 1)
        v += __shfl_xor_sync(0xffffffffu, v, o);

    // Lane 0: publish partial to L2 (st.global.cg — bypasses L1), arrive with
    // gpu-scope acq_rel atomic (release orders the store; acquire covers the
    // last warp's reads). No barriers, no smem, no MEMBAR on this path.
    unsigned prev = 0;
    if (lane == 0) {
        asm volatile(
            "st.global.cg.f32 [%1], %2;\n\t"
            "atom.acq_rel.gpu.global.add.u32 %0, [%3], 1;\n\t"
            : "=r"(prev)
            : "l"(&g_partial[blockIdx.x]), "f"(v), "l"(&g_count)
            : "memory");
    }
    // broadcast last-arriver flag to the whole warp (warp-uniform branch)
    const bool is_last =
        (__shfl_sync(0xffffffffu, prev, 0) == (unsigned)(NBLK - 1));

    if (is_last) {
        // fold 64 partials: 2 acquire loads per lane, fixed order -> deterministic
        float p0, p1;
        asm volatile("ld.acquire.gpu.global.f32 %0, [%1];"
                     : "=f"(p0) : "l"(&g_partial[lane]) : "memory");
        asm volatile("ld.acquire.gpu.global.f32 %0, [%1];"
                     : "=f"(p1) : "l"(&g_partial[lane + 32]) : "memory");
        float p = p0 + p1;
        #pragma unroll
        for (int o = 16; o; o >>= 1)
            p += __shfl_xor_sync(0xffffffffu, p, o);
        if (lane == 0) {
            *out = -(p / (float)DIM);
            g_count = 0;   // re-arm; visible at kernel boundary before next replay
        }
    }
}

extern "C" void kernel_launch(void* const* d_in, const int* in_sizes, int n_in,
                              void* d_out, int out_size) {
    const float* emb = (const float*)d_in[0];   // embeddings [10240, 32000] f32
    const int*   tgt = (const int*)d_in[1];     // targets [2048] i32

    mmi_fused_kernel<<<NBLK, TPB>>>(emb, tgt, (float*)d_out);
}